// round 10
// baseline (speedup 1.0000x reference)
#include <cuda_runtime.h>
#include <math.h>

typedef unsigned long long ull;

// Problem constants
#define B    512
#define IU   8
#define C    1152
#define J    10
#define S    16
#define NR   3
#define R    (B*IU)      // 4096

// Tiling
#define CG   32          // c's per block group
#define NCG  (C/CG)      // 36 c-groups -> 36 partial groups
#define CCB  8           // c's per subchunk
#define NSUB (CG/CCB)    // 4
#define BT   128         // b's per block
#define NBT  (B/BT)      // 4
#define NTHR 512
#define WJS  72          // smem ull stride per (c,j) row (padded from 64)
#define WROW 64          // gmem ull per (c,j) row
#define WSUB (CCB*J*WJS) // 5760 ull
#define XSUBF (CCB*BT*IU) // 8192 floats per x subchunk (UNduplicated)

// Scratch (__device__ globals; no allocation)
__device__ __align__(16) float g_xT[(size_t)C*R];       // plain x [c][b*8+i] 18.9MB
__device__ __align__(16) ull  g_Wp[(size_t)C*J*WROW];   // packed W (s,s+8)   5.9MB
__device__ float g_bA[C*J];                              // b after iter 1
__device__ __align__(16) ull  g_sp2[NCG][(size_t)J*B*8];   // s partials 11.8MB
__device__ __align__(16) ull  g_v2[(size_t)J*B*8];         // packed v
__device__ float g_bp[NBT][C*J];                            // delta_b partials

// SMEM layouts
struct SMemS {
    ull   Wp[2][WSUB];       // 92160 B
    float xf[2][XSUBF];      // 65536 B
    float ccs[CG*J];         // 1280 B
    float bn[CG*J];          // 1280 B
};
struct SMemB {
    ull   Wp[2][WSUB];       // 92160 B (double-buffered now)
    float xf[2][XSUBF];      // 65536 B
    float dsm[16*CCB*J];     // 5120 B
};

// ---- packed f32x2 helpers ------------------------------------------------
__device__ __forceinline__ void fma2(ull& d, ull a, ull b) {
    asm("fma.rn.f32x2 %0, %1, %2, %0;" : "+l"(d) : "l"(a), "l"(b));
}
__device__ __forceinline__ ull add2(ull a, ull b) {
    ull d; asm("add.rn.f32x2 %0, %1, %2;" : "=l"(d) : "l"(a), "l"(b)); return d;
}
__device__ __forceinline__ ull pack2(float lo, float hi) {
    return ((ull)__float_as_uint(hi) << 32) | (ull)__float_as_uint(lo);
}
__device__ __forceinline__ ull dup2(float f) {
    unsigned u = __float_as_uint(f); return ((ull)u << 32) | (ull)u;
}
__device__ __forceinline__ float lo2(ull v) { return __uint_as_float((unsigned)v); }
__device__ __forceinline__ float hi2(ull v) { return __uint_as_float((unsigned)(v >> 32)); }

// ---- cp.async helpers ----------------------------------------------------
__device__ __forceinline__ void cpa16(void* dst, const void* src) {
    unsigned s = (unsigned)__cvta_generic_to_shared(dst);
    asm volatile("cp.async.cg.shared.global [%0], [%1], 16;" :: "r"(s), "l"(src));
}
__device__ __forceinline__ void cpcommit() {
    asm volatile("cp.async.commit_group;" ::: "memory");
}
template <int N> __device__ __forceinline__ void cpwait() {
    asm volatile("cp.async.wait_group %0;" :: "n"(N) : "memory");
}

// ---------------------------------------------------------------------------
// Prep: x[b][i][c] -> g_xT[c][b*8+i] (plain float)
// ---------------------------------------------------------------------------
__global__ void k_transpose(const float* __restrict__ x) {
    __shared__ float t[32][33];
    int cb = blockIdx.x * 32, rb = blockIdx.y * 32;
    int tx = threadIdx.x, ty = threadIdx.y;
    #pragma unroll
    for (int k = 0; k < 32; k += 8)
        t[ty + k][tx] = x[(size_t)(rb + ty + k) * C + cb + tx];
    __syncthreads();
    #pragma unroll
    for (int k = 0; k < 32; k += 8)
        g_xT[(size_t)(cb + ty + k) * R + rb + tx] = t[tx][ty + k];
}

// Prep: W[c][j][s][i] -> g_Wp[cj][ih*32 + il*8 + sh] = (W[..sh..i], W[..sh+8..i])
__global__ void k_prepW(const float* __restrict__ W) {
    int gid = blockIdx.x * 256 + threadIdx.x;
    if (gid >= C * J * WROW) return;
    int sh = gid & 7, il = (gid >> 3) & 3, ih = (gid >> 5) & 1, cj = gid >> 6;
    int i = ih * 4 + il;
    float lo = W[((size_t)cj * 16 + sh) * 8 + i];
    float hi = W[((size_t)cj * 16 + sh + 8) * 8 + i];
    g_Wp[(size_t)cj * WROW + ih * 32 + il * 8 + sh] = pack2(lo, hi);
}

// ---------------------------------------------------------------------------
// cp.async stagers
// ---------------------------------------------------------------------------
__device__ __forceinline__ void issue_W(ull* Wb, int cstart, int tid) {
    const ull* src = g_Wp + (size_t)cstart * J * WROW;
    #pragma unroll
    for (int t = tid; t < CCB * J * 32; t += NTHR) {
        int row = t >> 5, ch = t & 31;
        cpa16(Wb + row * WJS + ch * 2, src + row * WROW + ch * 2);
    }
}
// x: 8192 floats = 2048 16B-chunks per subchunk (UNduplicated)
__device__ __forceinline__ void issue_x(float* xb, int cstart, int b0, int tid) {
    #pragma unroll
    for (int t = tid; t < XSUBF / 4; t += NTHR) {
        int cl = t >> 8, ch = t & 255;
        cpa16(xb + cl * (BT * IU) + ch * 4,
              g_xT + (size_t)(cstart + cl) * R + (size_t)b0 * IU + ch * 4);
    }
}

// ---------------------------------------------------------------------------
// K_s: partial s[j,b,(s,s+8)] over this block's 32 c's.
// MODE 1: recompute b-update + softmax in-block (from g_bp), rescale staged W
// in SMEM by cc. EPOCH selects whether prior b (g_bA) is added / persisted.
// MODE 0: first iteration, uniform cc folded as 0.1 postscale in k_rs.
// ---------------------------------------------------------------------------
template <int MODE, int EPOCH>
__global__ void __launch_bounds__(NTHR, 1) k_s() {
    extern __shared__ char smraw[];
    SMemS& sm = *(SMemS*)smraw;
    int tid = threadIdx.x;
    int cg = blockIdx.x, bt = blockIdx.y;
    int c0 = cg * CG, b0 = bt * BT;
    int sh  = tid & 7;
    int jb  = ((tid >> 3) & 1) * 5;
    int bt4 = tid >> 4;

    issue_W(sm.Wp[0], c0, tid);
    issue_x(sm.xf[0], c0, b0, tid);
    cpcommit();

    if (MODE == 1) {
        if (tid < CG * J) {
            int j = tid % J, c = c0 + tid / J;
            float d = g_bp[0][c * J + j] + g_bp[1][c * J + j]
                    + g_bp[2][c * J + j] + g_bp[3][c * J + j];
            float nb = d * (1.f / B);
            if (EPOCH == 1) nb += g_bA[c * J + j];
            sm.bn[tid] = nb;
            if (bt == 0 && EPOCH == 0) g_bA[c * J + j] = nb;
        }
        __syncthreads();
        if (tid < CG * J) {
            int cl = tid / J;
            float mx = sm.bn[cl * J];
            #pragma unroll
            for (int q = 1; q < J; q++) mx = fmaxf(mx, sm.bn[cl * J + q]);
            float su = 0.f;
            #pragma unroll
            for (int q = 0; q < J; q++) su += expf(sm.bn[cl * J + q] - mx);
            sm.ccs[tid] = expf(sm.bn[tid] - mx) / su;
        }
        // loop's post-wait __syncthreads orders ccs before first rescale read
    }

    ull acc[5][4];
    #pragma unroll
    for (int jj = 0; jj < 5; jj++)
        #pragma unroll
        for (int t = 0; t < 4; t++) acc[jj][t] = 0ull;

    for (int sc = 0; sc < NSUB; sc++) {
        if (sc > 0) __syncthreads();
        if (sc + 1 < NSUB) {
            issue_W(sm.Wp[(sc + 1) & 1], c0 + (sc + 1) * CCB, tid);
            issue_x(sm.xf[(sc + 1) & 1], c0 + (sc + 1) * CCB, b0, tid);
            cpcommit();
        }
        if (sc + 1 < NSUB) cpwait<1>(); else cpwait<0>();
        __syncthreads();
        ull* Wb = sm.Wp[sc & 1];
        const float* xb = sm.xf[sc & 1];

        if (MODE == 1) {
            const float* cs = sm.ccs + sc * CCB * J;
            #pragma unroll
            for (int t = tid; t < CCB * J * 64; t += NTHR) {
                int row = t >> 6;
                float cv = cs[row];
                ull w = Wb[row * WJS + (t & 63)];
                Wb[row * WJS + (t & 63)] = pack2(lo2(w) * cv, hi2(w) * cv);
            }
            __syncthreads();
        }

        #pragma unroll
        for (int cl = 0; cl < CCB; cl++) {
            const float* xrow = xb + (cl * BT + bt4 * 4) * IU;
            #pragma unroll
            for (int ih = 0; ih < 2; ih++) {
                ull xd_[4][4];
                #pragma unroll
                for (int t = 0; t < 4; t++) {
                    float4 xf4 = *(const float4*)(xrow + t * IU + ih * 4);
                    xd_[t][0] = dup2(xf4.x);
                    xd_[t][1] = dup2(xf4.y);
                    xd_[t][2] = dup2(xf4.z);
                    xd_[t][3] = dup2(xf4.w);
                }
                const ull* wb_ = Wb + (cl * J + jb) * WJS + ih * 32 + sh;
                #pragma unroll
                for (int jj = 0; jj < 5; jj++) {
                    const ull* w = wb_ + jj * WJS;
                    ull w0 = w[0], w1 = w[8], w2 = w[16], w3 = w[24];
                    #pragma unroll
                    for (int t = 0; t < 4; t++) {
                        fma2(acc[jj][t], w0, xd_[t][0]);
                        fma2(acc[jj][t], w1, xd_[t][1]);
                        fma2(acc[jj][t], w2, xd_[t][2]);
                        fma2(acc[jj][t], w3, xd_[t][3]);
                    }
                }
            }
        }
    }
    ull* spb = g_sp2[cg];
    #pragma unroll
    for (int jj = 0; jj < 5; jj++)
        #pragma unroll
        for (int t = 0; t < 4; t++)
            spb[((size_t)(jb + jj) * B + b0 + bt4 * 4 + t) * 8 + sh] = acc[jj][t];
}

// ---------------------------------------------------------------------------
// K_b: partial delta_b[c,j] = sum_{b in tile, s} v * u_hat. Raw W (no cc).
// W now double-buffered like k_s (removes the serialized W-staging bubble).
// ---------------------------------------------------------------------------
__global__ void __launch_bounds__(NTHR, 1) k_b() {
    extern __shared__ char smraw[];
    SMemB& sm = *(SMemB*)smraw;
    int tid = threadIdx.x;
    int cg = blockIdx.x, bt = blockIdx.y;
    int c0 = cg * CG, b0 = bt * BT;
    int sh  = tid & 7;
    int jb  = ((tid >> 3) & 1) * 5;
    int bt4 = tid >> 4;
    int warp = tid >> 5, lane = tid & 31;

    issue_W(sm.Wp[0], c0, tid);
    issue_x(sm.xf[0], c0, b0, tid);
    cpcommit();

    ull vv[5][4];
    #pragma unroll
    for (int jj = 0; jj < 5; jj++)
        #pragma unroll
        for (int t = 0; t < 4; t++)
            vv[jj][t] = g_v2[((size_t)(jb + jj) * B + b0 + bt4 * 4 + t) * 8 + sh];

    for (int sc = 0; sc < NSUB; sc++) {
        if (sc > 0) __syncthreads();         // dsm consumed; buffers reusable
        if (sc + 1 < NSUB) {
            issue_W(sm.Wp[(sc + 1) & 1], c0 + (sc + 1) * CCB, tid);
            issue_x(sm.xf[(sc + 1) & 1], c0 + (sc + 1) * CCB, b0, tid);
            cpcommit();
        }
        if (sc + 1 < NSUB) cpwait<1>(); else cpwait<0>();
        __syncthreads();
        const ull* Wb = sm.Wp[sc & 1];
        const float* xb = sm.xf[sc & 1];

        #pragma unroll 1
        for (int cl = 0; cl < CCB; cl++) {
            ull p2[5] = {0, 0, 0, 0, 0};
            const float* xrow = xb + (cl * BT + bt4 * 4) * IU;
            #pragma unroll
            for (int ih = 0; ih < 2; ih++) {
                ull xd_[4][4];
                #pragma unroll
                for (int t = 0; t < 4; t++) {
                    float4 xf4 = *(const float4*)(xrow + t * IU + ih * 4);
                    xd_[t][0] = dup2(xf4.x);
                    xd_[t][1] = dup2(xf4.y);
                    xd_[t][2] = dup2(xf4.z);
                    xd_[t][3] = dup2(xf4.w);
                }
                const ull* wb_ = Wb + (cl * J + jb) * WJS + ih * 32 + sh;
                #pragma unroll
                for (int jj = 0; jj < 5; jj++) {
                    const ull* w = wb_ + jj * WJS;
                    ull y0 = 0, y1 = 0, y2 = 0, y3 = 0;
                    #pragma unroll
                    for (int t = 0; t < 4; t++) {
                        fma2(y0, vv[jj][t], xd_[t][0]);
                        fma2(y1, vv[jj][t], xd_[t][1]);
                        fma2(y2, vv[jj][t], xd_[t][2]);
                        fma2(y3, vv[jj][t], xd_[t][3]);
                    }
                    fma2(p2[jj], w[0],  y0);
                    fma2(p2[jj], w[8],  y1);
                    fma2(p2[jj], w[16], y2);
                    fma2(p2[jj], w[24], y3);
                }
            }
            #pragma unroll
            for (int jj = 0; jj < 5; jj++) {
                float p = lo2(p2[jj]) + hi2(p2[jj]);
                p += __shfl_xor_sync(0xffffffffu, p, 1);
                p += __shfl_xor_sync(0xffffffffu, p, 2);
                p += __shfl_xor_sync(0xffffffffu, p, 4);
                p += __shfl_xor_sync(0xffffffffu, p, 16);
                if ((lane & 23) == 0)   // lanes 0 (jg0) and 8 (jg1)
                    sm.dsm[warp * (CCB * J) + cl * J + jb + jj] = p;
            }
        }
        __syncthreads();
        if (tid < CCB * J) {
            float s = 0.f;
            #pragma unroll
            for (int w = 0; w < 16; w++) s += sm.dsm[w * (CCB * J) + tid];
            g_bp[bt][(c0 + sc * CCB + tid / J) * J + tid % J] = s;
        }
    }
}

// ---------------------------------------------------------------------------
// Fused reduction + squash: each thread sums all 36 partials for a
// ulonglong2 (2 packed s-pairs), MLP ~36 independent 16B loads. 160 blocks.
// ---------------------------------------------------------------------------
__global__ void k_rs(float postscale, float* __restrict__ out) {
    int idx2 = blockIdx.x * 128 + threadIdx.x;   // [0, 20480)
    ull a0 = 0ull, a1 = 0ull, b0_ = 0ull, b1 = 0ull;
    #pragma unroll 6
    for (int p = 0; p < NCG; p += 2) {
        ulonglong2 v0 = ((const ulonglong2*)g_sp2[p])[idx2];
        ulonglong2 v1 = ((const ulonglong2*)g_sp2[p + 1])[idx2];
        a0 = add2(a0, v0.x); a1 = add2(a1, v0.y);
        b0_ = add2(b0_, v1.x); b1 = add2(b1, v1.y);
    }
    a0 = add2(a0, b0_); a1 = add2(a1, b1);
    float l0 = lo2(a0) * postscale, h0 = hi2(a0) * postscale;
    float l1 = lo2(a1) * postscale, h1 = hi2(a1) * postscale;
    float m = l0 * l0 + h0 * h0 + l1 * l1 + h1 * h1;
    m += __shfl_xor_sync(0xffffffffu, m, 1);
    m += __shfl_xor_sync(0xffffffffu, m, 2);
    float fac = sqrtf(m) / (1.f + m);
    l0 *= fac; h0 *= fac; l1 *= fac; h1 *= fac;
    ((ulonglong2*)g_v2)[idx2] = make_ulonglong2(pack2(l0, h0), pack2(l1, h1));
    if (out) {
        int shq = idx2 & 3;                  // s-quad: covers s = 2q, 2q+1
        int jb_ = idx2 >> 2;
        int b   = jb_ & (B - 1);
        int j   = jb_ >> 9;
        float* o = out + (b * J + j) * S + shq * 2;
        *(float2*)(o)     = make_float2(l0, l1);
        *(float2*)(o + 8) = make_float2(h0, h1);
    }
}

// ---------------------------------------------------------------------------
extern "C" void kernel_launch(void* const* d_in, const int* in_sizes, int n_in,
                              void* d_out, int out_size) {
    const float* x = (const float*)d_in[0];   // [512][8][1152]
    const float* W = (const float*)d_in[1];   // [1152][10][16][8]
    float* out = (float*)d_out;               // [512][10][16]

    cudaFuncSetAttribute(k_s<0,0>, cudaFuncAttributeMaxDynamicSharedMemorySize,
                         (int)sizeof(SMemS));
    cudaFuncSetAttribute(k_s<1,0>, cudaFuncAttributeMaxDynamicSharedMemorySize,
                         (int)sizeof(SMemS));
    cudaFuncSetAttribute(k_s<1,1>, cudaFuncAttributeMaxDynamicSharedMemorySize,
                         (int)sizeof(SMemS));
    cudaFuncSetAttribute(k_b, cudaFuncAttributeMaxDynamicSharedMemorySize,
                         (int)sizeof(SMemB));

    k_transpose<<<dim3(C / 32, R / 32), dim3(32, 8)>>>(x);
    k_prepW<<<(C * J * WROW + 255) / 256, 256>>>(W);

    dim3 grid(NCG, NBT);

    // t = 0: uniform cc = 1/J folded as postscale
    k_s<0,0><<<grid, NTHR, sizeof(SMemS)>>>();
    k_rs<<<160, 128>>>(0.1f, nullptr);

    // t = 1
    k_b<<<grid, NTHR, sizeof(SMemB)>>>();
    k_s<1,0><<<grid, NTHR, sizeof(SMemS)>>>();
    k_rs<<<160, 128>>>(1.f, nullptr);

    // t = 2
    k_b<<<grid, NTHR, sizeof(SMemB)>>>();
    k_s<1,1><<<grid, NTHR, sizeof(SMemS)>>>();
    k_rs<<<160, 128>>>(1.f, out);
}

// round 12
// speedup vs baseline: 1.0199x; 1.0199x over previous
#include <cuda_runtime.h>
#include <math.h>

typedef unsigned long long ull;

// Problem constants
#define B    512
#define IU   8
#define C    1152
#define J    10
#define S    16
#define NR   3
#define R    (B*IU)      // 4096

// Tiling
#define CG   32          // c's per block group
#define NCG  (C/CG)      // 36 c-groups -> 36 partial groups
#define CCB  8           // c's per subchunk
#define NSUB (CG/CCB)    // 4
#define BT   128         // b's per block
#define NBT  (B/BT)      // 4
#define NTHR 512
#define WJS  72          // smem ull stride per (c,j) row (padded from 64)
#define WROW 64          // gmem ull per (c,j) row
#define WSUB (CCB*J*WJS) // 5760 ull
#define XSUBF (CCB*BT*IU) // 8192 floats per x subchunk (UNduplicated)

// Scratch (__device__ globals; no allocation)
__device__ __align__(16) float g_xT[(size_t)C*R];       // plain x [c][b*8+i] 18.9MB
__device__ __align__(16) ull  g_Wp[(size_t)C*J*WROW];   // packed W (s,s+8)   5.9MB
__device__ float g_bA[C*J];                              // b after iter 1
__device__ __align__(16) ull  g_sp2[NCG][(size_t)J*B*8];   // s partials 11.8MB
__device__ __align__(16) ull  g_v2[(size_t)J*B*8];         // packed v
__device__ float g_bp[NBT][C*J];                            // delta_b partials

// SMEM layouts
struct SMemS {
    ull   Wp[2][WSUB];       // 92160 B
    float xf[2][XSUBF];      // 65536 B
    float ccs[CG*J];         // 1280 B
    float bn[CG*J];          // 1280 B
};
struct SMemB {
    ull   Wp[WSUB];          // 46080 B
    float xf[2][XSUBF];      // 65536 B
    float dsm[16*CCB*J];     // 5120 B
};

// ---- packed f32x2 helpers ------------------------------------------------
__device__ __forceinline__ void fma2(ull& d, ull a, ull b) {
    asm("fma.rn.f32x2 %0, %1, %2, %0;" : "+l"(d) : "l"(a), "l"(b));
}
__device__ __forceinline__ ull add2(ull a, ull b) {
    ull d; asm("add.rn.f32x2 %0, %1, %2;" : "=l"(d) : "l"(a), "l"(b)); return d;
}
__device__ __forceinline__ ull pack2(float lo, float hi) {
    return ((ull)__float_as_uint(hi) << 32) | (ull)__float_as_uint(lo);
}
__device__ __forceinline__ ull dup2(float f) {
    unsigned u = __float_as_uint(f); return ((ull)u << 32) | (ull)u;
}
__device__ __forceinline__ float lo2(ull v) { return __uint_as_float((unsigned)v); }
__device__ __forceinline__ float hi2(ull v) { return __uint_as_float((unsigned)(v >> 32)); }

// ---- cp.async helpers ----------------------------------------------------
__device__ __forceinline__ void cpa16(void* dst, const void* src) {
    unsigned s = (unsigned)__cvta_generic_to_shared(dst);
    asm volatile("cp.async.cg.shared.global [%0], [%1], 16;" :: "r"(s), "l"(src));
}
__device__ __forceinline__ void cpcommit() {
    asm volatile("cp.async.commit_group;" ::: "memory");
}
template <int N> __device__ __forceinline__ void cpwait() {
    asm volatile("cp.async.wait_group %0;" :: "n"(N) : "memory");
}

// ---------------------------------------------------------------------------
// Prep: x[b][i][c] -> g_xT[c][b*8+i] (plain float)
// ---------------------------------------------------------------------------
__global__ void k_transpose(const float* __restrict__ x) {
    __shared__ float t[32][33];
    int cb = blockIdx.x * 32, rb = blockIdx.y * 32;
    int tx = threadIdx.x, ty = threadIdx.y;
    #pragma unroll
    for (int k = 0; k < 32; k += 8)
        t[ty + k][tx] = x[(size_t)(rb + ty + k) * C + cb + tx];
    __syncthreads();
    #pragma unroll
    for (int k = 0; k < 32; k += 8)
        g_xT[(size_t)(cb + ty + k) * R + rb + tx] = t[tx][ty + k];
}

// Prep: W[c][j][s][i] -> g_Wp[cj][ih*32 + il*8 + sh] = (W[..sh..i], W[..sh+8..i])
__global__ void k_prepW(const float* __restrict__ W) {
    int gid = blockIdx.x * 256 + threadIdx.x;
    if (gid >= C * J * WROW) return;
    int sh = gid & 7, il = (gid >> 3) & 3, ih = (gid >> 5) & 1, cj = gid >> 6;
    int i = ih * 4 + il;
    float lo = W[((size_t)cj * 16 + sh) * 8 + i];
    float hi = W[((size_t)cj * 16 + sh + 8) * 8 + i];
    g_Wp[(size_t)cj * WROW + ih * 32 + il * 8 + sh] = pack2(lo, hi);
}

// ---------------------------------------------------------------------------
// cp.async stagers
// ---------------------------------------------------------------------------
__device__ __forceinline__ void issue_W(ull* Wb, int cstart, int tid) {
    const ull* src = g_Wp + (size_t)cstart * J * WROW;
    #pragma unroll
    for (int t = tid; t < CCB * J * 32; t += NTHR) {
        int row = t >> 5, ch = t & 31;
        cpa16(Wb + row * WJS + ch * 2, src + row * WROW + ch * 2);
    }
}
// x: 8192 floats = 2048 16B-chunks per subchunk (UNduplicated)
__device__ __forceinline__ void issue_x(float* xb, int cstart, int b0, int tid) {
    #pragma unroll
    for (int t = tid; t < XSUBF / 4; t += NTHR) {
        int cl = t >> 8, ch = t & 255;
        cpa16(xb + cl * (BT * IU) + ch * 4,
              g_xT + (size_t)(cstart + cl) * R + (size_t)b0 * IU + ch * 4);
    }
}

// ---------------------------------------------------------------------------
// K_s: partial s[j,b,(s,s+8)] over this block's 32 c's.
// MODE 1: recompute b-update + softmax in-block (from g_bp), rescale staged W
// in SMEM by cc. EPOCH selects whether prior b (g_bA) is added / persisted.
// MODE 0: first iteration, uniform cc folded as 0.1 postscale in k_rs.
// ---------------------------------------------------------------------------
template <int MODE, int EPOCH>
__global__ void __launch_bounds__(NTHR, 1) k_s() {
    extern __shared__ char smraw[];
    SMemS& sm = *(SMemS*)smraw;
    int tid = threadIdx.x;
    int cg = blockIdx.x, bt = blockIdx.y;
    int c0 = cg * CG, b0 = bt * BT;
    int sh  = tid & 7;
    int jb  = ((tid >> 3) & 1) * 5;
    int bt4 = tid >> 4;

    issue_W(sm.Wp[0], c0, tid);
    issue_x(sm.xf[0], c0, b0, tid);
    cpcommit();

    if (MODE == 1) {
        if (tid < CG * J) {
            int j = tid % J, c = c0 + tid / J;
            float d = g_bp[0][c * J + j] + g_bp[1][c * J + j]
                    + g_bp[2][c * J + j] + g_bp[3][c * J + j];
            float nb = d * (1.f / B);
            if (EPOCH == 1) nb += g_bA[c * J + j];
            sm.bn[tid] = nb;
            if (bt == 0 && EPOCH == 0) g_bA[c * J + j] = nb;
        }
        __syncthreads();
        if (tid < CG * J) {
            int cl = tid / J;
            float mx = sm.bn[cl * J];
            #pragma unroll
            for (int q = 1; q < J; q++) mx = fmaxf(mx, sm.bn[cl * J + q]);
            float su = 0.f;
            #pragma unroll
            for (int q = 0; q < J; q++) su += expf(sm.bn[cl * J + q] - mx);
            sm.ccs[tid] = expf(sm.bn[tid] - mx) / su;
        }
        // loop's post-wait __syncthreads orders ccs before first rescale read
    }

    ull acc[5][4];
    #pragma unroll
    for (int jj = 0; jj < 5; jj++)
        #pragma unroll
        for (int t = 0; t < 4; t++) acc[jj][t] = 0ull;

    for (int sc = 0; sc < NSUB; sc++) {
        if (sc > 0) __syncthreads();
        if (sc + 1 < NSUB) {
            issue_W(sm.Wp[(sc + 1) & 1], c0 + (sc + 1) * CCB, tid);
            issue_x(sm.xf[(sc + 1) & 1], c0 + (sc + 1) * CCB, b0, tid);
            cpcommit();
        }
        if (sc + 1 < NSUB) cpwait<1>(); else cpwait<0>();
        __syncthreads();
        ull* Wb = sm.Wp[sc & 1];
        const float* xb = sm.xf[sc & 1];

        if (MODE == 1) {
            const float* cs = sm.ccs + sc * CCB * J;
            #pragma unroll
            for (int t = tid; t < CCB * J * 64; t += NTHR) {
                int row = t >> 6;
                float cv = cs[row];
                ull w = Wb[row * WJS + (t & 63)];
                Wb[row * WJS + (t & 63)] = pack2(lo2(w) * cv, hi2(w) * cv);
            }
            __syncthreads();
        }

        #pragma unroll
        for (int cl = 0; cl < CCB; cl++) {
            const float* xrow = xb + (cl * BT + bt4 * 4) * IU;
            #pragma unroll
            for (int ih = 0; ih < 2; ih++) {
                ull xd_[4][4];
                #pragma unroll
                for (int t = 0; t < 4; t++) {
                    float4 xf4 = *(const float4*)(xrow + t * IU + ih * 4);
                    xd_[t][0] = dup2(xf4.x);
                    xd_[t][1] = dup2(xf4.y);
                    xd_[t][2] = dup2(xf4.z);
                    xd_[t][3] = dup2(xf4.w);
                }
                const ull* wb_ = Wb + (cl * J + jb) * WJS + ih * 32 + sh;
                #pragma unroll
                for (int jj = 0; jj < 5; jj++) {
                    const ull* w = wb_ + jj * WJS;
                    ull w0 = w[0], w1 = w[8], w2 = w[16], w3 = w[24];
                    #pragma unroll
                    for (int t = 0; t < 4; t++) {
                        fma2(acc[jj][t], w0, xd_[t][0]);
                        fma2(acc[jj][t], w1, xd_[t][1]);
                        fma2(acc[jj][t], w2, xd_[t][2]);
                        fma2(acc[jj][t], w3, xd_[t][3]);
                    }
                }
            }
        }
    }
    ull* spb = g_sp2[cg];
    #pragma unroll
    for (int jj = 0; jj < 5; jj++)
        #pragma unroll
        for (int t = 0; t < 4; t++)
            spb[((size_t)(jb + jj) * B + b0 + bt4 * 4 + t) * 8 + sh] = acc[jj][t];
}

// ---------------------------------------------------------------------------
// K_b: partial delta_b[c,j] = sum_{b in tile, s} v * u_hat. Raw W (no cc).
// (R9 version: single W buffer.)
// ---------------------------------------------------------------------------
__global__ void __launch_bounds__(NTHR, 1) k_b() {
    extern __shared__ char smraw[];
    SMemB& sm = *(SMemB*)smraw;
    int tid = threadIdx.x;
    int cg = blockIdx.x, bt = blockIdx.y;
    int c0 = cg * CG, b0 = bt * BT;
    int sh  = tid & 7;
    int jb  = ((tid >> 3) & 1) * 5;
    int bt4 = tid >> 4;
    int warp = tid >> 5, lane = tid & 31;

    issue_W(sm.Wp, c0, tid);
    issue_x(sm.xf[0], c0, b0, tid);
    cpcommit();

    ull vv[5][4];
    #pragma unroll
    for (int jj = 0; jj < 5; jj++)
        #pragma unroll
        for (int t = 0; t < 4; t++)
            vv[jj][t] = g_v2[((size_t)(jb + jj) * B + b0 + bt4 * 4 + t) * 8 + sh];

    for (int sc = 0; sc < NSUB; sc++) {
        if (sc > 0) {
            __syncthreads();                 // protects Wp + dsm + x buffer reuse
            issue_W(sm.Wp, c0 + sc * CCB, tid);
            cpcommit();
        }
        if (sc + 1 < NSUB) {
            issue_x(sm.xf[(sc + 1) & 1], c0 + (sc + 1) * CCB, b0, tid);
            cpcommit();
        }
        if (sc + 1 < NSUB) cpwait<1>(); else cpwait<0>();
        __syncthreads();
        const float* xb = sm.xf[sc & 1];

        #pragma unroll 1
        for (int cl = 0; cl < CCB; cl++) {
            ull p2[5] = {0, 0, 0, 0, 0};
            const float* xrow = xb + (cl * BT + bt4 * 4) * IU;
            #pragma unroll
            for (int ih = 0; ih < 2; ih++) {
                ull xd_[4][4];
                #pragma unroll
                for (int t = 0; t < 4; t++) {
                    float4 xf4 = *(const float4*)(xrow + t * IU + ih * 4);
                    xd_[t][0] = dup2(xf4.x);
                    xd_[t][1] = dup2(xf4.y);
                    xd_[t][2] = dup2(xf4.z);
                    xd_[t][3] = dup2(xf4.w);
                }
                const ull* wb_ = sm.Wp + (cl * J + jb) * WJS + ih * 32 + sh;
                #pragma unroll
                for (int jj = 0; jj < 5; jj++) {
                    const ull* w = wb_ + jj * WJS;
                    ull y0 = 0, y1 = 0, y2 = 0, y3 = 0;
                    #pragma unroll
                    for (int t = 0; t < 4; t++) {
                        fma2(y0, vv[jj][t], xd_[t][0]);
                        fma2(y1, vv[jj][t], xd_[t][1]);
                        fma2(y2, vv[jj][t], xd_[t][2]);
                        fma2(y3, vv[jj][t], xd_[t][3]);
                    }
                    fma2(p2[jj], w[0],  y0);
                    fma2(p2[jj], w[8],  y1);
                    fma2(p2[jj], w[16], y2);
                    fma2(p2[jj], w[24], y3);
                }
            }
            #pragma unroll
            for (int jj = 0; jj < 5; jj++) {
                float p = lo2(p2[jj]) + hi2(p2[jj]);
                p += __shfl_xor_sync(0xffffffffu, p, 1);
                p += __shfl_xor_sync(0xffffffffu, p, 2);
                p += __shfl_xor_sync(0xffffffffu, p, 4);
                p += __shfl_xor_sync(0xffffffffu, p, 16);
                if ((lane & 23) == 0)   // lanes 0 (jg0) and 8 (jg1)
                    sm.dsm[warp * (CCB * J) + cl * J + jb + jj] = p;
            }
        }
        __syncthreads();
        if (tid < CCB * J) {
            float s = 0.f;
            #pragma unroll
            for (int w = 0; w < 16; w++) s += sm.dsm[w * (CCB * J) + tid];
            g_bp[bt][(c0 + sc * CCB + tid / J) * J + tid % J] = s;
        }
    }
}

// ---------------------------------------------------------------------------
// Single-stage reduction + squash: 40960 threads (160 x 256), one packed ull
// each, 36 fully-unrolled coalesced 8B loads with 4 independent add chains.
// Per-SM in-flight bytes ~2x the DRAM BW*latency product -> DRAM-rate bound.
// ---------------------------------------------------------------------------
__global__ void __launch_bounds__(256) k_rs(float postscale, float* __restrict__ out) {
    int idx = blockIdx.x * 256 + threadIdx.x;   // [0, 40960)
    ull a0 = 0ull, a1 = 0ull, a2 = 0ull, a3 = 0ull;
    #pragma unroll
    for (int p = 0; p < NCG; p += 4) {
        a0 = add2(a0, g_sp2[p][idx]);
        a1 = add2(a1, g_sp2[p + 1][idx]);
        a2 = add2(a2, g_sp2[p + 2][idx]);
        a3 = add2(a3, g_sp2[p + 3][idx]);
    }
    ull a = add2(add2(a0, a1), add2(a2, a3));
    float lo = lo2(a) * postscale;
    float hi = hi2(a) * postscale;
    float m = lo * lo + hi * hi;
    m += __shfl_xor_sync(0xffffffffu, m, 1);
    m += __shfl_xor_sync(0xffffffffu, m, 2);
    m += __shfl_xor_sync(0xffffffffu, m, 4);
    float fac = sqrtf(m) / (1.f + m);
    float vlo = lo * fac, vhi = hi * fac;
    g_v2[idx] = pack2(vlo, vhi);
    if (out) {
        int sh = idx & 7;
        int b  = (idx >> 3) & (B - 1);
        int j  = idx >> 12;
        out[(b * J + j) * S + sh]     = vlo;
        out[(b * J + j) * S + sh + 8] = vhi;
    }
}

// ---------------------------------------------------------------------------
extern "C" void kernel_launch(void* const* d_in, const int* in_sizes, int n_in,
                              void* d_out, int out_size) {
    const float* x = (const float*)d_in[0];   // [512][8][1152]
    const float* W = (const float*)d_in[1];   // [1152][10][16][8]
    float* out = (float*)d_out;               // [512][10][16]

    cudaFuncSetAttribute(k_s<0,0>, cudaFuncAttributeMaxDynamicSharedMemorySize,
                         (int)sizeof(SMemS));
    cudaFuncSetAttribute(k_s<1,0>, cudaFuncAttributeMaxDynamicSharedMemorySize,
                         (int)sizeof(SMemS));
    cudaFuncSetAttribute(k_s<1,1>, cudaFuncAttributeMaxDynamicSharedMemorySize,
                         (int)sizeof(SMemS));
    cudaFuncSetAttribute(k_b, cudaFuncAttributeMaxDynamicSharedMemorySize,
                         (int)sizeof(SMemB));

    k_transpose<<<dim3(C / 32, R / 32), dim3(32, 8)>>>(x);
    k_prepW<<<(C * J * WROW + 255) / 256, 256>>>(W);

    dim3 grid(NCG, NBT);

    // t = 0: uniform cc = 1/J folded as postscale
    k_s<0,0><<<grid, NTHR, sizeof(SMemS)>>>();
    k_rs<<<160, 256>>>(0.1f, nullptr);

    // t = 1
    k_b<<<grid, NTHR, sizeof(SMemB)>>>();
    k_s<1,0><<<grid, NTHR, sizeof(SMemS)>>>();
    k_rs<<<160, 256>>>(1.f, nullptr);

    // t = 2
    k_b<<<grid, NTHR, sizeof(SMemB)>>>();
    k_s<1,1><<<grid, NTHR, sizeof(SMemS)>>>();
    k_rs<<<160, 256>>>(1.f, out);
}

// round 13
// speedup vs baseline: 1.0397x; 1.0195x over previous
#include <cuda_runtime.h>
#include <math.h>

typedef unsigned long long ull;

// Problem constants
#define B    512
#define IU   8
#define C    1152
#define J    10
#define S    16
#define NR   3
#define R    (B*IU)      // 4096

// Tiling
#define CG   32          // c's per block group
#define NCG  (C/CG)      // 36 c-groups -> 36 partial groups
#define CCB  8           // c's per subchunk
#define NSUB (CG/CCB)    // 4
#define BT   128         // b's per block
#define NBT  (B/BT)      // 4
#define NTHR 512
#define WJS  72          // smem ull stride per (c,j) row (padded from 64)
#define WROW 64          // gmem ull per (c,j) row
#define WSUB (CCB*J*WJS) // 5760 ull
#define XSUBF (CCB*BT*IU) // 8192 floats per x subchunk (UNduplicated)

// Scratch (__device__ globals; no allocation)
__device__ __align__(16) float g_xT[(size_t)C*R];       // plain x [c][b*8+i] 18.9MB
__device__ __align__(16) ull  g_Wp[(size_t)C*J*WROW];   // packed W (s,s+8)   5.9MB
__device__ float g_bA[C*J];                              // b after iter 1
__device__ __align__(16) ull  g_sp2[NCG][(size_t)J*B*8];   // s partials 11.8MB
__device__ __align__(16) ull  g_v2[(size_t)J*B*8];         // packed v
__device__ float g_bp[NBT][C*J];                            // delta_b partials

// SMEM layouts
struct SMemS {
    ull   Wp[2][WSUB];       // 92160 B
    float xf[2][XSUBF];      // 65536 B
    float ccs[CG*J];         // 1280 B
    float bn[CG*J];          // 1280 B
};
struct SMemB {
    ull   Wp[WSUB];          // 46080 B
    float xf[2][XSUBF];      // 65536 B
    float dsm[16*CCB*J];     // 5120 B
};

// ---- packed f32x2 helpers ------------------------------------------------
__device__ __forceinline__ void fma2(ull& d, ull a, ull b) {
    asm("fma.rn.f32x2 %0, %1, %2, %0;" : "+l"(d) : "l"(a), "l"(b));
}
__device__ __forceinline__ ull add2(ull a, ull b) {
    ull d; asm("add.rn.f32x2 %0, %1, %2;" : "=l"(d) : "l"(a), "l"(b)); return d;
}
__device__ __forceinline__ ull pack2(float lo, float hi) {
    return ((ull)__float_as_uint(hi) << 32) | (ull)__float_as_uint(lo);
}
__device__ __forceinline__ ull dup2(float f) {
    unsigned u = __float_as_uint(f); return ((ull)u << 32) | (ull)u;
}
__device__ __forceinline__ float lo2(ull v) { return __uint_as_float((unsigned)v); }
__device__ __forceinline__ float hi2(ull v) { return __uint_as_float((unsigned)(v >> 32)); }

// ---- cp.async helpers ----------------------------------------------------
__device__ __forceinline__ void cpa16(void* dst, const void* src) {
    unsigned s = (unsigned)__cvta_generic_to_shared(dst);
    asm volatile("cp.async.cg.shared.global [%0], [%1], 16;" :: "r"(s), "l"(src));
}
__device__ __forceinline__ void cpcommit() {
    asm volatile("cp.async.commit_group;" ::: "memory");
}
template <int N> __device__ __forceinline__ void cpwait() {
    asm volatile("cp.async.wait_group %0;" :: "n"(N) : "memory");
}

// ---------------------------------------------------------------------------
// Prep: x[b][i][c] -> g_xT[c][b*8+i] (plain float)
// ---------------------------------------------------------------------------
__global__ void k_transpose(const float* __restrict__ x) {
    __shared__ float t[32][33];
    int cb = blockIdx.x * 32, rb = blockIdx.y * 32;
    int tx = threadIdx.x, ty = threadIdx.y;
    #pragma unroll
    for (int k = 0; k < 32; k += 8)
        t[ty + k][tx] = x[(size_t)(rb + ty + k) * C + cb + tx];
    __syncthreads();
    #pragma unroll
    for (int k = 0; k < 32; k += 8)
        g_xT[(size_t)(cb + ty + k) * R + rb + tx] = t[tx][ty + k];
}

// Prep: W[c][j][s][i] -> g_Wp[cj][ih*32 + il*8 + sh] = (W[..sh..i], W[..sh+8..i])
__global__ void k_prepW(const float* __restrict__ W) {
    int gid = blockIdx.x * 256 + threadIdx.x;
    if (gid >= C * J * WROW) return;
    int sh = gid & 7, il = (gid >> 3) & 3, ih = (gid >> 5) & 1, cj = gid >> 6;
    int i = ih * 4 + il;
    float lo = W[((size_t)cj * 16 + sh) * 8 + i];
    float hi = W[((size_t)cj * 16 + sh + 8) * 8 + i];
    g_Wp[(size_t)cj * WROW + ih * 32 + il * 8 + sh] = pack2(lo, hi);
}

// ---------------------------------------------------------------------------
// cp.async stagers
// ---------------------------------------------------------------------------
__device__ __forceinline__ void issue_W(ull* Wb, int cstart, int tid) {
    const ull* src = g_Wp + (size_t)cstart * J * WROW;
    #pragma unroll
    for (int t = tid; t < CCB * J * 32; t += NTHR) {
        int row = t >> 5, ch = t & 31;
        cpa16(Wb + row * WJS + ch * 2, src + row * WROW + ch * 2);
    }
}
// x: 8192 floats = 2048 16B-chunks per subchunk (UNduplicated)
__device__ __forceinline__ void issue_x(float* xb, int cstart, int b0, int tid) {
    #pragma unroll
    for (int t = tid; t < XSUBF / 4; t += NTHR) {
        int cl = t >> 8, ch = t & 255;
        cpa16(xb + cl * (BT * IU) + ch * 4,
              g_xT + (size_t)(cstart + cl) * R + (size_t)b0 * IU + ch * 4);
    }
}

// ---------------------------------------------------------------------------
// K_s: partial s[j,b,(s,s+8)] over this block's 32 c's.
// MODE 1: recompute b-update + softmax in-block (from g_bp), rescale staged W
// in SMEM by cc. EPOCH selects whether prior b (g_bA) is added / persisted.
// MODE 0: first iteration, uniform cc folded as 0.1 postscale in k_rs.
// ---------------------------------------------------------------------------
template <int MODE, int EPOCH>
__global__ void __launch_bounds__(NTHR, 1) k_s() {
    extern __shared__ char smraw[];
    SMemS& sm = *(SMemS*)smraw;
    int tid = threadIdx.x;
    int cg = blockIdx.x, bt = blockIdx.y;
    int c0 = cg * CG, b0 = bt * BT;
    int sh  = tid & 7;
    int jb  = ((tid >> 3) & 1) * 5;
    int bt4 = tid >> 4;

    issue_W(sm.Wp[0], c0, tid);
    issue_x(sm.xf[0], c0, b0, tid);
    cpcommit();

    if (MODE == 1) {
        if (tid < CG * J) {
            int j = tid % J, c = c0 + tid / J;
            float d = g_bp[0][c * J + j] + g_bp[1][c * J + j]
                    + g_bp[2][c * J + j] + g_bp[3][c * J + j];
            float nb = d * (1.f / B);
            if (EPOCH == 1) nb += g_bA[c * J + j];
            sm.bn[tid] = nb;
            if (bt == 0 && EPOCH == 0) g_bA[c * J + j] = nb;
        }
        __syncthreads();
        if (tid < CG * J) {
            int cl = tid / J;
            float mx = sm.bn[cl * J];
            #pragma unroll
            for (int q = 1; q < J; q++) mx = fmaxf(mx, sm.bn[cl * J + q]);
            float su = 0.f;
            #pragma unroll
            for (int q = 0; q < J; q++) su += expf(sm.bn[cl * J + q] - mx);
            sm.ccs[tid] = expf(sm.bn[tid] - mx) / su;
        }
        // loop's post-wait __syncthreads orders ccs before first rescale read
    }

    ull acc[5][4];
    #pragma unroll
    for (int jj = 0; jj < 5; jj++)
        #pragma unroll
        for (int t = 0; t < 4; t++) acc[jj][t] = 0ull;

    for (int sc = 0; sc < NSUB; sc++) {
        if (sc > 0) __syncthreads();
        if (sc + 1 < NSUB) {
            issue_W(sm.Wp[(sc + 1) & 1], c0 + (sc + 1) * CCB, tid);
            issue_x(sm.xf[(sc + 1) & 1], c0 + (sc + 1) * CCB, b0, tid);
            cpcommit();
        }
        if (sc + 1 < NSUB) cpwait<1>(); else cpwait<0>();
        __syncthreads();
        ull* Wb = sm.Wp[sc & 1];
        const float* xb = sm.xf[sc & 1];

        if (MODE == 1) {
            const float* cs = sm.ccs + sc * CCB * J;
            #pragma unroll
            for (int t = tid; t < CCB * J * 64; t += NTHR) {
                int row = t >> 6;
                float cv = cs[row];
                ull w = Wb[row * WJS + (t & 63)];
                Wb[row * WJS + (t & 63)] = pack2(lo2(w) * cv, hi2(w) * cv);
            }
            __syncthreads();
        }

        #pragma unroll
        for (int cl = 0; cl < CCB; cl++) {
            const float* xrow = xb + (cl * BT + bt4 * 4) * IU;
            #pragma unroll
            for (int ih = 0; ih < 2; ih++) {
                ull xd_[4][4];
                #pragma unroll
                for (int t = 0; t < 4; t++) {
                    float4 xf4 = *(const float4*)(xrow + t * IU + ih * 4);
                    xd_[t][0] = dup2(xf4.x);
                    xd_[t][1] = dup2(xf4.y);
                    xd_[t][2] = dup2(xf4.z);
                    xd_[t][3] = dup2(xf4.w);
                }
                const ull* wb_ = Wb + (cl * J + jb) * WJS + ih * 32 + sh;
                #pragma unroll
                for (int jj = 0; jj < 5; jj++) {
                    const ull* w = wb_ + jj * WJS;
                    ull w0 = w[0], w1 = w[8], w2 = w[16], w3 = w[24];
                    #pragma unroll
                    for (int t = 0; t < 4; t++) {
                        fma2(acc[jj][t], w0, xd_[t][0]);
                        fma2(acc[jj][t], w1, xd_[t][1]);
                        fma2(acc[jj][t], w2, xd_[t][2]);
                        fma2(acc[jj][t], w3, xd_[t][3]);
                    }
                }
            }
        }
    }
    ull* spb = g_sp2[cg];
    #pragma unroll
    for (int jj = 0; jj < 5; jj++)
        #pragma unroll
        for (int t = 0; t < 4; t++)
            spb[((size_t)(jb + jj) * B + b0 + bt4 * 4 + t) * 8 + sh] = acc[jj][t];
}

// ---------------------------------------------------------------------------
// K_b: partial delta_b[c,j] = sum_{b in tile, s} v * u_hat. Raw W (no cc).
// Direct-u form: u[t] = sum_i w_i (x) x_{t,i} (8 fma2), then p += vv (x) u
// (1 fma2) -> 180 fma2/cl vs 200 for the y-factorization.
// ---------------------------------------------------------------------------
__global__ void __launch_bounds__(NTHR, 1) k_b() {
    extern __shared__ char smraw[];
    SMemB& sm = *(SMemB*)smraw;
    int tid = threadIdx.x;
    int cg = blockIdx.x, bt = blockIdx.y;
    int c0 = cg * CG, b0 = bt * BT;
    int sh  = tid & 7;
    int jb  = ((tid >> 3) & 1) * 5;
    int bt4 = tid >> 4;
    int warp = tid >> 5, lane = tid & 31;

    issue_W(sm.Wp, c0, tid);
    issue_x(sm.xf[0], c0, b0, tid);
    cpcommit();

    ull vv[5][4];
    #pragma unroll
    for (int jj = 0; jj < 5; jj++)
        #pragma unroll
        for (int t = 0; t < 4; t++)
            vv[jj][t] = g_v2[((size_t)(jb + jj) * B + b0 + bt4 * 4 + t) * 8 + sh];

    for (int sc = 0; sc < NSUB; sc++) {
        if (sc > 0) {
            __syncthreads();                 // protects Wp + dsm + x buffer reuse
            issue_W(sm.Wp, c0 + sc * CCB, tid);
            cpcommit();
        }
        if (sc + 1 < NSUB) {
            issue_x(sm.xf[(sc + 1) & 1], c0 + (sc + 1) * CCB, b0, tid);
            cpcommit();
        }
        if (sc + 1 < NSUB) cpwait<1>(); else cpwait<0>();
        __syncthreads();
        const float* xb = sm.xf[sc & 1];

        #pragma unroll 1
        for (int cl = 0; cl < CCB; cl++) {
            ull p2[5] = {0, 0, 0, 0, 0};
            const float* xrow = xb + (cl * BT + bt4 * 4) * IU;
            // load + duplicate all 8 i's for the 4 b's of this thread
            ull xd_[4][8];
            #pragma unroll
            for (int t = 0; t < 4; t++) {
                float4 xa = *(const float4*)(xrow + t * IU);
                float4 xc = *(const float4*)(xrow + t * IU + 4);
                xd_[t][0] = dup2(xa.x); xd_[t][1] = dup2(xa.y);
                xd_[t][2] = dup2(xa.z); xd_[t][3] = dup2(xa.w);
                xd_[t][4] = dup2(xc.x); xd_[t][5] = dup2(xc.y);
                xd_[t][6] = dup2(xc.z); xd_[t][7] = dup2(xc.w);
            }
            const ull* wb_ = sm.Wp + (cl * J + jb) * WJS + sh;
            #pragma unroll
            for (int jj = 0; jj < 5; jj++) {
                const ull* w = wb_ + jj * WJS;
                ull w0 = w[0],  w1 = w[8],  w2 = w[16], w3 = w[24];
                ull w4 = w[32], w5 = w[40], w6 = w[48], w7 = w[56];
                #pragma unroll
                for (int t = 0; t < 4; t++) {
                    ull u;
                    asm("mul.rn.f32x2 %0, %1, %2;" : "=l"(u) : "l"(w0), "l"(xd_[t][0]));
                    fma2(u, w1, xd_[t][1]);
                    fma2(u, w2, xd_[t][2]);
                    fma2(u, w3, xd_[t][3]);
                    fma2(u, w4, xd_[t][4]);
                    fma2(u, w5, xd_[t][5]);
                    fma2(u, w6, xd_[t][6]);
                    fma2(u, w7, xd_[t][7]);
                    fma2(p2[jj], vv[jj][t], u);
                }
            }
            #pragma unroll
            for (int jj = 0; jj < 5; jj++) {
                float p = lo2(p2[jj]) + hi2(p2[jj]);
                p += __shfl_xor_sync(0xffffffffu, p, 1);
                p += __shfl_xor_sync(0xffffffffu, p, 2);
                p += __shfl_xor_sync(0xffffffffu, p, 4);
                p += __shfl_xor_sync(0xffffffffu, p, 16);
                if ((lane & 23) == 0)   // lanes 0 (jg0) and 8 (jg1)
                    sm.dsm[warp * (CCB * J) + cl * J + jb + jj] = p;
            }
        }
        __syncthreads();
        if (tid < CCB * J) {
            float s = 0.f;
            #pragma unroll
            for (int w = 0; w < 16; w++) s += sm.dsm[w * (CCB * J) + tid];
            g_bp[bt][(c0 + sc * CCB + tid / J) * J + tid % J] = s;
        }
    }
}

// ---------------------------------------------------------------------------
// Single-stage reduction + squash. All 36 partial loads issued into an
// explicit register array BEFORE summation (no 32-reg MLP throttle).
// ---------------------------------------------------------------------------
__global__ void __launch_bounds__(256) k_rs(float postscale, float* __restrict__ out) {
    int idx = blockIdx.x * 256 + threadIdx.x;   // [0, 40960)
    ull v[NCG];
    #pragma unroll
    for (int p = 0; p < NCG; p++) v[p] = g_sp2[p][idx];
    ull a0 = v[0], a1 = v[1], a2 = v[2], a3 = v[3];
    #pragma unroll
    for (int p = 4; p < NCG; p += 4) {
        a0 = add2(a0, v[p]);
        a1 = add2(a1, v[p + 1]);
        a2 = add2(a2, v[p + 2]);
        a3 = add2(a3, v[p + 3]);
    }
    ull a = add2(add2(a0, a1), add2(a2, a3));
    float lo = lo2(a) * postscale;
    float hi = hi2(a) * postscale;
    float m = lo * lo + hi * hi;
    m += __shfl_xor_sync(0xffffffffu, m, 1);
    m += __shfl_xor_sync(0xffffffffu, m, 2);
    m += __shfl_xor_sync(0xffffffffu, m, 4);
    float fac = sqrtf(m) / (1.f + m);
    float vlo = lo * fac, vhi = hi * fac;
    g_v2[idx] = pack2(vlo, vhi);
    if (out) {
        int sh = idx & 7;
        int b  = (idx >> 3) & (B - 1);
        int j  = idx >> 12;
        out[(b * J + j) * S + sh]     = vlo;
        out[(b * J + j) * S + sh + 8] = vhi;
    }
}

// ---------------------------------------------------------------------------
extern "C" void kernel_launch(void* const* d_in, const int* in_sizes, int n_in,
                              void* d_out, int out_size) {
    const float* x = (const float*)d_in[0];   // [512][8][1152]
    const float* W = (const float*)d_in[1];   // [1152][10][16][8]
    float* out = (float*)d_out;               // [512][10][16]

    cudaFuncSetAttribute(k_s<0,0>, cudaFuncAttributeMaxDynamicSharedMemorySize,
                         (int)sizeof(SMemS));
    cudaFuncSetAttribute(k_s<1,0>, cudaFuncAttributeMaxDynamicSharedMemorySize,
                         (int)sizeof(SMemS));
    cudaFuncSetAttribute(k_s<1,1>, cudaFuncAttributeMaxDynamicSharedMemorySize,
                         (int)sizeof(SMemS));
    cudaFuncSetAttribute(k_b, cudaFuncAttributeMaxDynamicSharedMemorySize,
                         (int)sizeof(SMemB));

    k_transpose<<<dim3(C / 32, R / 32), dim3(32, 8)>>>(x);
    k_prepW<<<(C * J * WROW + 255) / 256, 256>>>(W);

    dim3 grid(NCG, NBT);

    // t = 0: uniform cc = 1/J folded as postscale
    k_s<0,0><<<grid, NTHR, sizeof(SMemS)>>>();
    k_rs<<<160, 256>>>(0.1f, nullptr);

    // t = 1
    k_b<<<grid, NTHR, sizeof(SMemB)>>>();
    k_s<1,0><<<grid, NTHR, sizeof(SMemS)>>>();
    k_rs<<<160, 256>>>(1.f, nullptr);

    // t = 2
    k_b<<<grid, NTHR, sizeof(SMemB)>>>();
    k_s<1,1><<<grid, NTHR, sizeof(SMemS)>>>();
    k_rs<<<160, 256>>>(1.f, out);
}

// round 15
// speedup vs baseline: 1.0521x; 1.0119x over previous
#include <cuda_runtime.h>
#include <math.h>

typedef unsigned long long ull;

// Problem constants
#define B    512
#define IU   8
#define C    1152
#define J    10
#define S    16
#define NR   3
#define R    (B*IU)      // 4096

// Tiling
#define CG   32          // c's per block group
#define NCG  (C/CG)      // 36 c-groups -> 36 partial groups
#define CCB  8           // c's per subchunk
#define NSUB (CG/CCB)    // 4
#define BT   128         // b's per block
#define NBT  (B/BT)      // 4
#define NTHR 512
#define WJS  72          // smem ull stride per (c,j) row (padded from 64)
#define WROW 64          // gmem ull per (c,j) row
#define WSUB (CCB*J*WJS) // 5760 ull
#define XSUBF (CCB*BT*IU) // 8192 floats per x subchunk (UNduplicated)

// Scratch (__device__ globals; no allocation)
__device__ __align__(16) float g_xT[(size_t)C*R];       // plain x [c][b*8+i] 18.9MB
__device__ __align__(16) ull  g_Wp[(size_t)C*J*WROW];   // packed W (s,s+8)   5.9MB
__device__ float g_bA[C*J];                              // b after iter 1
__device__ __align__(16) ull  g_sp2[NCG][(size_t)J*B*8];   // s partials 11.8MB
__device__ __align__(16) ull  g_v2[(size_t)J*B*8];         // packed v
__device__ float g_bp[NBT][C*J];                            // delta_b partials

// SMEM layouts
struct SMemS {
    ull   Wp[2][WSUB];       // 92160 B
    float xf[2][XSUBF];      // 65536 B
    float ccs[CG*J];         // 1280 B
    float bn[CG*J];          // 1280 B
};
struct SMemB {
    ull   Wp[WSUB];          // 46080 B
    float xf[2][XSUBF];      // 65536 B
    float dsm[16*CCB*J];     // 5120 B
};

// ---- packed f32x2 helpers ------------------------------------------------
__device__ __forceinline__ void fma2(ull& d, ull a, ull b) {
    asm("fma.rn.f32x2 %0, %1, %2, %0;" : "+l"(d) : "l"(a), "l"(b));
}
__device__ __forceinline__ ull add2(ull a, ull b) {
    ull d; asm("add.rn.f32x2 %0, %1, %2;" : "=l"(d) : "l"(a), "l"(b)); return d;
}
__device__ __forceinline__ ull pack2(float lo, float hi) {
    return ((ull)__float_as_uint(hi) << 32) | (ull)__float_as_uint(lo);
}
__device__ __forceinline__ ull dup2(float f) {
    unsigned u = __float_as_uint(f); return ((ull)u << 32) | (ull)u;
}
__device__ __forceinline__ float lo2(ull v) { return __uint_as_float((unsigned)v); }
__device__ __forceinline__ float hi2(ull v) { return __uint_as_float((unsigned)(v >> 32)); }

// ---- cp.async helpers ----------------------------------------------------
__device__ __forceinline__ void cpa16(void* dst, const void* src) {
    unsigned s = (unsigned)__cvta_generic_to_shared(dst);
    asm volatile("cp.async.cg.shared.global [%0], [%1], 16;" :: "r"(s), "l"(src));
}
__device__ __forceinline__ void cpcommit() {
    asm volatile("cp.async.commit_group;" ::: "memory");
}
template <int N> __device__ __forceinline__ void cpwait() {
    asm volatile("cp.async.wait_group %0;" :: "n"(N) : "memory");
}

// ---------------------------------------------------------------------------
// Prep: x[b][i][c] -> g_xT[c][b*8+i] (plain float)
// ---------------------------------------------------------------------------
__global__ void k_transpose(const float* __restrict__ x) {
    __shared__ float t[32][33];
    int cb = blockIdx.x * 32, rb = blockIdx.y * 32;
    int tx = threadIdx.x, ty = threadIdx.y;
    #pragma unroll
    for (int k = 0; k < 32; k += 8)
        t[ty + k][tx] = x[(size_t)(rb + ty + k) * C + cb + tx];
    __syncthreads();
    #pragma unroll
    for (int k = 0; k < 32; k += 8)
        g_xT[(size_t)(cb + ty + k) * R + rb + tx] = t[tx][ty + k];
}

// Prep: W[c][j][s][i] -> g_Wp[cj][ih*32 + il*8 + sh] = (W[..sh..i], W[..sh+8..i])
__global__ void k_prepW(const float* __restrict__ W) {
    int gid = blockIdx.x * 256 + threadIdx.x;
    if (gid >= C * J * WROW) return;
    int sh = gid & 7, il = (gid >> 3) & 3, ih = (gid >> 5) & 1, cj = gid >> 6;
    int i = ih * 4 + il;
    float lo = W[((size_t)cj * 16 + sh) * 8 + i];
    float hi = W[((size_t)cj * 16 + sh + 8) * 8 + i];
    g_Wp[(size_t)cj * WROW + ih * 32 + il * 8 + sh] = pack2(lo, hi);
}

// ---------------------------------------------------------------------------
// cp.async stagers
// ---------------------------------------------------------------------------
__device__ __forceinline__ void issue_W(ull* Wb, int cstart, int tid) {
    const ull* src = g_Wp + (size_t)cstart * J * WROW;
    #pragma unroll
    for (int t = tid; t < CCB * J * 32; t += NTHR) {
        int row = t >> 5, ch = t & 31;
        cpa16(Wb + row * WJS + ch * 2, src + row * WROW + ch * 2);
    }
}
// x: 8192 floats = 2048 16B-chunks per subchunk (UNduplicated)
__device__ __forceinline__ void issue_x(float* xb, int cstart, int b0, int tid) {
    #pragma unroll
    for (int t = tid; t < XSUBF / 4; t += NTHR) {
        int cl = t >> 8, ch = t & 255;
        cpa16(xb + cl * (BT * IU) + ch * 4,
              g_xT + (size_t)(cstart + cl) * R + (size_t)b0 * IU + ch * 4);
    }
}

// ---------------------------------------------------------------------------
// K_s: partial s[j,b,(s,s+8)] over this block's 32 c's.
// MODE 1: recompute b-update + softmax in-block (from g_bp), rescale staged W
// in SMEM by cc. EPOCH selects whether prior b (g_bA) is added / persisted.
// MODE 0: first iteration, uniform cc folded as 0.1 postscale in k_rs.
// ---------------------------------------------------------------------------
template <int MODE, int EPOCH>
__global__ void __launch_bounds__(NTHR, 1) k_s() {
    extern __shared__ char smraw[];
    SMemS& sm = *(SMemS*)smraw;
    int tid = threadIdx.x;
    int cg = blockIdx.x, bt = blockIdx.y;
    int c0 = cg * CG, b0 = bt * BT;
    int sh  = tid & 7;
    int jb  = ((tid >> 3) & 1) * 5;
    int bt4 = tid >> 4;

    issue_W(sm.Wp[0], c0, tid);
    issue_x(sm.xf[0], c0, b0, tid);
    cpcommit();

    if (MODE == 1) {
        if (tid < CG * J) {
            int j = tid % J, c = c0 + tid / J;
            float d = g_bp[0][c * J + j] + g_bp[1][c * J + j]
                    + g_bp[2][c * J + j] + g_bp[3][c * J + j];
            float nb = d * (1.f / B);
            if (EPOCH == 1) nb += g_bA[c * J + j];
            sm.bn[tid] = nb;
            if (bt == 0 && EPOCH == 0) g_bA[c * J + j] = nb;
        }
        __syncthreads();
        if (tid < CG * J) {
            int cl = tid / J;
            float mx = sm.bn[cl * J];
            #pragma unroll
            for (int q = 1; q < J; q++) mx = fmaxf(mx, sm.bn[cl * J + q]);
            float su = 0.f;
            #pragma unroll
            for (int q = 0; q < J; q++) su += expf(sm.bn[cl * J + q] - mx);
            sm.ccs[tid] = expf(sm.bn[tid] - mx) / su;
        }
        // loop's post-wait __syncthreads orders ccs before first rescale read
    }

    ull acc[5][4];
    #pragma unroll
    for (int jj = 0; jj < 5; jj++)
        #pragma unroll
        for (int t = 0; t < 4; t++) acc[jj][t] = 0ull;

    for (int sc = 0; sc < NSUB; sc++) {
        if (sc > 0) __syncthreads();
        if (sc + 1 < NSUB) {
            issue_W(sm.Wp[(sc + 1) & 1], c0 + (sc + 1) * CCB, tid);
            issue_x(sm.xf[(sc + 1) & 1], c0 + (sc + 1) * CCB, b0, tid);
            cpcommit();
        }
        if (sc + 1 < NSUB) cpwait<1>(); else cpwait<0>();
        __syncthreads();
        ull* Wb = sm.Wp[sc & 1];
        const float* xb = sm.xf[sc & 1];

        if (MODE == 1) {
            const float* cs = sm.ccs + sc * CCB * J;
            #pragma unroll
            for (int t = tid; t < CCB * J * 64; t += NTHR) {
                int row = t >> 6;
                float cv = cs[row];
                ull w = Wb[row * WJS + (t & 63)];
                Wb[row * WJS + (t & 63)] = pack2(lo2(w) * cv, hi2(w) * cv);
            }
            __syncthreads();
        }

        #pragma unroll
        for (int cl = 0; cl < CCB; cl++) {
            const float* xrow = xb + (cl * BT + bt4 * 4) * IU;
            #pragma unroll
            for (int ih = 0; ih < 2; ih++) {
                ull xd_[4][4];
                #pragma unroll
                for (int t = 0; t < 4; t++) {
                    float4 xf4 = *(const float4*)(xrow + t * IU + ih * 4);
                    xd_[t][0] = dup2(xf4.x);
                    xd_[t][1] = dup2(xf4.y);
                    xd_[t][2] = dup2(xf4.z);
                    xd_[t][3] = dup2(xf4.w);
                }
                const ull* wb_ = Wb + (cl * J + jb) * WJS + ih * 32 + sh;
                #pragma unroll
                for (int jj = 0; jj < 5; jj++) {
                    const ull* w = wb_ + jj * WJS;
                    ull w0 = w[0], w1 = w[8], w2 = w[16], w3 = w[24];
                    #pragma unroll
                    for (int t = 0; t < 4; t++) {
                        fma2(acc[jj][t], w0, xd_[t][0]);
                        fma2(acc[jj][t], w1, xd_[t][1]);
                        fma2(acc[jj][t], w2, xd_[t][2]);
                        fma2(acc[jj][t], w3, xd_[t][3]);
                    }
                }
            }
        }
    }
    ull* spb = g_sp2[cg];
    #pragma unroll
    for (int jj = 0; jj < 5; jj++)
        #pragma unroll
        for (int t = 0; t < 4; t++)
            spb[((size_t)(jb + jj) * B + b0 + bt4 * 4 + t) * 8 + sh] = acc[jj][t];
}

// ---------------------------------------------------------------------------
// K_b: partial delta_b[c,j] = sum_{b in tile, s} v * u_hat. Raw W (no cc).
// Direct-u form: u[t] = sum_i w_i (x) x_{t,i} (8 fma2), then p += vv (x) u
// (1 fma2) -> 180 fma2/cl vs 200 for the y-factorization.
// ---------------------------------------------------------------------------
__global__ void __launch_bounds__(NTHR, 1) k_b() {
    extern __shared__ char smraw[];
    SMemB& sm = *(SMemB*)smraw;
    int tid = threadIdx.x;
    int cg = blockIdx.x, bt = blockIdx.y;
    int c0 = cg * CG, b0 = bt * BT;
    int sh  = tid & 7;
    int jb  = ((tid >> 3) & 1) * 5;
    int bt4 = tid >> 4;
    int warp = tid >> 5, lane = tid & 31;

    issue_W(sm.Wp, c0, tid);
    issue_x(sm.xf[0], c0, b0, tid);
    cpcommit();

    ull vv[5][4];
    #pragma unroll
    for (int jj = 0; jj < 5; jj++)
        #pragma unroll
        for (int t = 0; t < 4; t++)
            vv[jj][t] = g_v2[((size_t)(jb + jj) * B + b0 + bt4 * 4 + t) * 8 + sh];

    for (int sc = 0; sc < NSUB; sc++) {
        if (sc > 0) {
            __syncthreads();                 // protects Wp + dsm + x buffer reuse
            issue_W(sm.Wp, c0 + sc * CCB, tid);
            cpcommit();
        }
        if (sc + 1 < NSUB) {
            issue_x(sm.xf[(sc + 1) & 1], c0 + (sc + 1) * CCB, b0, tid);
            cpcommit();
        }
        if (sc + 1 < NSUB) cpwait<1>(); else cpwait<0>();
        __syncthreads();
        const float* xb = sm.xf[sc & 1];

        #pragma unroll 1
        for (int cl = 0; cl < CCB; cl++) {
            ull p2[5] = {0, 0, 0, 0, 0};
            const float* xrow = xb + (cl * BT + bt4 * 4) * IU;
            // load + duplicate all 8 i's for the 4 b's of this thread
            ull xd_[4][8];
            #pragma unroll
            for (int t = 0; t < 4; t++) {
                float4 xa = *(const float4*)(xrow + t * IU);
                float4 xc = *(const float4*)(xrow + t * IU + 4);
                xd_[t][0] = dup2(xa.x); xd_[t][1] = dup2(xa.y);
                xd_[t][2] = dup2(xa.z); xd_[t][3] = dup2(xa.w);
                xd_[t][4] = dup2(xc.x); xd_[t][5] = dup2(xc.y);
                xd_[t][6] = dup2(xc.z); xd_[t][7] = dup2(xc.w);
            }
            const ull* wb_ = sm.Wp + (cl * J + jb) * WJS + sh;
            #pragma unroll
            for (int jj = 0; jj < 5; jj++) {
                const ull* w = wb_ + jj * WJS;
                ull w0 = w[0],  w1 = w[8],  w2 = w[16], w3 = w[24];
                ull w4 = w[32], w5 = w[40], w6 = w[48], w7 = w[56];
                #pragma unroll
                for (int t = 0; t < 4; t++) {
                    ull u;
                    asm("mul.rn.f32x2 %0, %1, %2;" : "=l"(u) : "l"(w0), "l"(xd_[t][0]));
                    fma2(u, w1, xd_[t][1]);
                    fma2(u, w2, xd_[t][2]);
                    fma2(u, w3, xd_[t][3]);
                    fma2(u, w4, xd_[t][4]);
                    fma2(u, w5, xd_[t][5]);
                    fma2(u, w6, xd_[t][6]);
                    fma2(u, w7, xd_[t][7]);
                    fma2(p2[jj], vv[jj][t], u);
                }
            }
            #pragma unroll
            for (int jj = 0; jj < 5; jj++) {
                float p = lo2(p2[jj]) + hi2(p2[jj]);
                p += __shfl_xor_sync(0xffffffffu, p, 1);
                p += __shfl_xor_sync(0xffffffffu, p, 2);
                p += __shfl_xor_sync(0xffffffffu, p, 4);
                p += __shfl_xor_sync(0xffffffffu, p, 16);
                if ((lane & 23) == 0)   // lanes 0 (jg0) and 8 (jg1)
                    sm.dsm[warp * (CCB * J) + cl * J + jb + jj] = p;
            }
        }
        __syncthreads();
        if (tid < CCB * J) {
            float s = 0.f;
            #pragma unroll
            for (int w = 0; w < 16; w++) s += sm.dsm[w * (CCB * J) + tid];
            g_bp[bt][(c0 + sc * CCB + tid / J) * J + tid % J] = s;
        }
    }
}

// ---------------------------------------------------------------------------
// Reduction + squash, 512 threads/block: upper half sums partials 18..35,
// lower half sums 0..17; halves meet through SMEM. 2x thread count buys the
// DRAM MLP that ptxas's 32-reg budget refused to provide.
// ---------------------------------------------------------------------------
__global__ void __launch_bounds__(512) k_rs(float postscale, float* __restrict__ out) {
    __shared__ ull sh2[256];
    int half = threadIdx.x >> 8;           // 0 or 1
    int t    = threadIdx.x & 255;
    int idx  = blockIdx.x * 256 + t;       // [0, 40960)
    int p0   = half * (NCG / 2);

    ull a0 = g_sp2[p0][idx];
    ull a1 = g_sp2[p0 + 1][idx];
    ull a2 = g_sp2[p0 + 2][idx];
    ull a3 = g_sp2[p0 + 3][idx];
    #pragma unroll
    for (int p = 4; p < NCG / 2 - 2; p += 4) {
        a0 = add2(a0, g_sp2[p0 + p][idx]);
        a1 = add2(a1, g_sp2[p0 + p + 1][idx]);
        a2 = add2(a2, g_sp2[p0 + p + 2][idx]);
        a3 = add2(a3, g_sp2[p0 + p + 3][idx]);
    }
    a0 = add2(a0, g_sp2[p0 + 16][idx]);
    a1 = add2(a1, g_sp2[p0 + 17][idx]);
    ull a = add2(add2(a0, a1), add2(a2, a3));

    if (half) sh2[t] = a;
    __syncthreads();
    if (half) return;
    a = add2(a, sh2[t]);

    float lo = lo2(a) * postscale;
    float hi = hi2(a) * postscale;
    float m = lo * lo + hi * hi;
    m += __shfl_xor_sync(0xffffffffu, m, 1);
    m += __shfl_xor_sync(0xffffffffu, m, 2);
    m += __shfl_xor_sync(0xffffffffu, m, 4);
    float fac = sqrtf(m) / (1.f + m);
    float vlo = lo * fac, vhi = hi * fac;
    g_v2[idx] = pack2(vlo, vhi);
    if (out) {
        int sh = idx & 7;
        int b  = (idx >> 3) & (B - 1);
        int j  = idx >> 12;
        out[(b * J + j) * S + sh]     = vlo;
        out[(b * J + j) * S + sh + 8] = vhi;
    }
}

// ---------------------------------------------------------------------------
extern "C" void kernel_launch(void* const* d_in, const int* in_sizes, int n_in,
                              void* d_out, int out_size) {
    const float* x = (const float*)d_in[0];   // [512][8][1152]
    const float* W = (const float*)d_in[1];   // [1152][10][16][8]
    float* out = (float*)d_out;               // [512][10][16]

    cudaFuncSetAttribute(k_s<0,0>, cudaFuncAttributeMaxDynamicSharedMemorySize,
                         (int)sizeof(SMemS));
    cudaFuncSetAttribute(k_s<1,0>, cudaFuncAttributeMaxDynamicSharedMemorySize,
                         (int)sizeof(SMemS));
    cudaFuncSetAttribute(k_s<1,1>, cudaFuncAttributeMaxDynamicSharedMemorySize,
                         (int)sizeof(SMemS));
    cudaFuncSetAttribute(k_b, cudaFuncAttributeMaxDynamicSharedMemorySize,
                         (int)sizeof(SMemB));

    k_transpose<<<dim3(C / 32, R / 32), dim3(32, 8)>>>(x);
    k_prepW<<<(C * J * WROW + 255) / 256, 256>>>(W);

    dim3 grid(NCG, NBT);

    // t = 0: uniform cc = 1/J folded as postscale
    k_s<0,0><<<grid, NTHR, sizeof(SMemS)>>>();
    k_rs<<<160, 512>>>(0.1f, nullptr);

    // t = 1
    k_b<<<grid, NTHR, sizeof(SMemB)>>>();
    k_s<1,0><<<grid, NTHR, sizeof(SMemS)>>>();
    k_rs<<<160, 512>>>(1.f, nullptr);

    // t = 2
    k_b<<<grid, NTHR, sizeof(SMemB)>>>();
    k_s<1,1><<<grid, NTHR, sizeof(SMemS)>>>();
    k_rs<<<160, 512>>>(1.f, out);
}

// round 16
// speedup vs baseline: 1.0610x; 1.0085x over previous
#include <cuda_runtime.h>
#include <math.h>

typedef unsigned long long ull;

// Problem constants
#define B    512
#define IU   8
#define C    1152
#define J    10
#define S    16
#define NR   3
#define R    (B*IU)      // 4096

// Tiling
#define CG   32          // c's per block group
#define NCG  (C/CG)      // 36 c-groups -> 36 partial groups
#define CCB  8           // c's per subchunk
#define NSUB (CG/CCB)    // 4
#define BT   128         // b's per block
#define NBT  (B/BT)      // 4
#define NTHR 512
#define WJS  72          // smem ull stride per (c,j) row (padded from 64)
#define WROW 64          // gmem ull per (c,j) row
#define WSUB (CCB*J*WJS) // 5760 ull
#define XSUBF (CCB*BT*IU) // 8192 floats per x subchunk (UNduplicated)

// Scratch (__device__ globals; no allocation)
__device__ __align__(16) float g_xT[(size_t)C*R];       // plain x [c][b*8+i] 18.9MB
__device__ __align__(16) ull  g_Wp[(size_t)C*J*WROW];   // packed W (s,s+8)   5.9MB
__device__ float g_bA[C*J];                              // b after iter 1
__device__ __align__(16) ull  g_sp2[NCG][(size_t)J*B*8];   // s partials 11.8MB
__device__ __align__(16) ull  g_v2[(size_t)J*B*8];         // packed v
__device__ float g_bp[NBT][C*J];                            // delta_b partials

// SMEM layouts
struct SMemS {
    ull   Wp[2][WSUB];       // 92160 B
    float xf[2][XSUBF];      // 65536 B
    float ccs[CG*J];         // 1280 B
    float bn[CG*J];          // 1280 B
};
struct SMemB {
    ull   Wp[WSUB];          // 46080 B
    float xf[2][XSUBF];      // 65536 B
    float dsm[16*CCB*J];     // 5120 B
};

// ---- packed f32x2 helpers ------------------------------------------------
__device__ __forceinline__ void fma2(ull& d, ull a, ull b) {
    asm("fma.rn.f32x2 %0, %1, %2, %0;" : "+l"(d) : "l"(a), "l"(b));
}
__device__ __forceinline__ ull add2(ull a, ull b) {
    ull d; asm("add.rn.f32x2 %0, %1, %2;" : "=l"(d) : "l"(a), "l"(b)); return d;
}
__device__ __forceinline__ ull pack2(float lo, float hi) {
    return ((ull)__float_as_uint(hi) << 32) | (ull)__float_as_uint(lo);
}
__device__ __forceinline__ ull dup2(float f) {
    unsigned u = __float_as_uint(f); return ((ull)u << 32) | (ull)u;
}
__device__ __forceinline__ float lo2(ull v) { return __uint_as_float((unsigned)v); }
__device__ __forceinline__ float hi2(ull v) { return __uint_as_float((unsigned)(v >> 32)); }

// ---- cp.async helpers ----------------------------------------------------
__device__ __forceinline__ void cpa16(void* dst, const void* src) {
    unsigned s = (unsigned)__cvta_generic_to_shared(dst);
    asm volatile("cp.async.cg.shared.global [%0], [%1], 16;" :: "r"(s), "l"(src));
}
__device__ __forceinline__ void cpcommit() {
    asm volatile("cp.async.commit_group;" ::: "memory");
}
template <int N> __device__ __forceinline__ void cpwait() {
    asm volatile("cp.async.wait_group %0;" :: "n"(N) : "memory");
}

// ---- PDL (programmatic dependent launch) helpers --------------------------
__device__ __forceinline__ void gdc_launch() {
    asm volatile("griddepcontrol.launch_dependents;");
}
__device__ __forceinline__ void gdc_wait() {
    asm volatile("griddepcontrol.wait;" ::: "memory");
}

// ---------------------------------------------------------------------------
// Prep: x[b][i][c] -> g_xT[c][b*8+i] (plain float)
// ---------------------------------------------------------------------------
__global__ void k_transpose(const float* __restrict__ x) {
    gdc_launch();
    __shared__ float t[32][33];
    int cb = blockIdx.x * 32, rb = blockIdx.y * 32;
    int tx = threadIdx.x, ty = threadIdx.y;
    #pragma unroll
    for (int k = 0; k < 32; k += 8)
        t[ty + k][tx] = x[(size_t)(rb + ty + k) * C + cb + tx];
    __syncthreads();
    #pragma unroll
    for (int k = 0; k < 32; k += 8)
        g_xT[(size_t)(cb + ty + k) * R + rb + tx] = t[tx][ty + k];
}

// Prep: W[c][j][s][i] -> g_Wp[cj][ih*32 + il*8 + sh] = (W[..sh..i], W[..sh+8..i])
__global__ void k_prepW(const float* __restrict__ W) {
    gdc_launch();
    int gid = blockIdx.x * 256 + threadIdx.x;
    if (gid >= C * J * WROW) return;
    int sh = gid & 7, il = (gid >> 3) & 3, ih = (gid >> 5) & 1, cj = gid >> 6;
    int i = ih * 4 + il;
    float lo = W[((size_t)cj * 16 + sh) * 8 + i];
    float hi = W[((size_t)cj * 16 + sh + 8) * 8 + i];
    g_Wp[(size_t)cj * WROW + ih * 32 + il * 8 + sh] = pack2(lo, hi);
}

// ---------------------------------------------------------------------------
// cp.async stagers
// ---------------------------------------------------------------------------
__device__ __forceinline__ void issue_W(ull* Wb, int cstart, int tid) {
    const ull* src = g_Wp + (size_t)cstart * J * WROW;
    #pragma unroll
    for (int t = tid; t < CCB * J * 32; t += NTHR) {
        int row = t >> 5, ch = t & 31;
        cpa16(Wb + row * WJS + ch * 2, src + row * WROW + ch * 2);
    }
}
// x: 8192 floats = 2048 16B-chunks per subchunk (UNduplicated)
__device__ __forceinline__ void issue_x(float* xb, int cstart, int b0, int tid) {
    #pragma unroll
    for (int t = tid; t < XSUBF / 4; t += NTHR) {
        int cl = t >> 8, ch = t & 255;
        cpa16(xb + cl * (BT * IU) + ch * 4,
              g_xT + (size_t)(cstart + cl) * R + (size_t)b0 * IU + ch * 4);
    }
}

// ---------------------------------------------------------------------------
// K_s: partial s[j,b,(s,s+8)] over this block's 32 c's.
// MODE 1: recompute b-update + softmax in-block (from g_bp), rescale staged W
// in SMEM by cc. EPOCH selects whether prior b (g_bA) is added / persisted.
// MODE 0: first iteration, uniform cc folded as 0.1 postscale in k_rs.
// PDL: MODE 0 waits BEFORE staging (g_xT/g_Wp come from the immediately
// preceding prep kernels); MODE 1 stages first (static data), waits before
// reading g_bp (written by the immediately preceding k_b).
// ---------------------------------------------------------------------------
template <int MODE, int EPOCH>
__global__ void __launch_bounds__(NTHR, 1) k_s() {
    extern __shared__ char smraw[];
    SMemS& sm = *(SMemS*)smraw;
    int tid = threadIdx.x;
    int cg = blockIdx.x, bt = blockIdx.y;
    int c0 = cg * CG, b0 = bt * BT;
    int sh  = tid & 7;
    int jb  = ((tid >> 3) & 1) * 5;
    int bt4 = tid >> 4;

    gdc_launch();
    if (MODE == 0) gdc_wait();      // staging sources written by prep kernels

    issue_W(sm.Wp[0], c0, tid);
    issue_x(sm.xf[0], c0, b0, tid);
    cpcommit();

    if (MODE == 1) {
        gdc_wait();                 // g_bp written by the preceding k_b
        if (tid < CG * J) {
            int j = tid % J, c = c0 + tid / J;
            float d = g_bp[0][c * J + j] + g_bp[1][c * J + j]
                    + g_bp[2][c * J + j] + g_bp[3][c * J + j];
            float nb = d * (1.f / B);
            if (EPOCH == 1) nb += g_bA[c * J + j];
            sm.bn[tid] = nb;
            if (bt == 0 && EPOCH == 0) g_bA[c * J + j] = nb;
        }
        __syncthreads();
        if (tid < CG * J) {
            int cl = tid / J;
            float mx = sm.bn[cl * J];
            #pragma unroll
            for (int q = 1; q < J; q++) mx = fmaxf(mx, sm.bn[cl * J + q]);
            float su = 0.f;
            #pragma unroll
            for (int q = 0; q < J; q++) su += expf(sm.bn[cl * J + q] - mx);
            sm.ccs[tid] = expf(sm.bn[tid] - mx) / su;
        }
        // loop's post-wait __syncthreads orders ccs before first rescale read
    }

    ull acc[5][4];
    #pragma unroll
    for (int jj = 0; jj < 5; jj++)
        #pragma unroll
        for (int t = 0; t < 4; t++) acc[jj][t] = 0ull;

    for (int sc = 0; sc < NSUB; sc++) {
        if (sc > 0) __syncthreads();
        if (sc + 1 < NSUB) {
            issue_W(sm.Wp[(sc + 1) & 1], c0 + (sc + 1) * CCB, tid);
            issue_x(sm.xf[(sc + 1) & 1], c0 + (sc + 1) * CCB, b0, tid);
            cpcommit();
        }
        if (sc + 1 < NSUB) cpwait<1>(); else cpwait<0>();
        __syncthreads();
        ull* Wb = sm.Wp[sc & 1];
        const float* xb = sm.xf[sc & 1];

        if (MODE == 1) {
            const float* cs = sm.ccs + sc * CCB * J;
            #pragma unroll
            for (int t = tid; t < CCB * J * 64; t += NTHR) {
                int row = t >> 6;
                float cv = cs[row];
                ull w = Wb[row * WJS + (t & 63)];
                Wb[row * WJS + (t & 63)] = pack2(lo2(w) * cv, hi2(w) * cv);
            }
            __syncthreads();
        }

        #pragma unroll
        for (int cl = 0; cl < CCB; cl++) {
            const float* xrow = xb + (cl * BT + bt4 * 4) * IU;
            #pragma unroll
            for (int ih = 0; ih < 2; ih++) {
                ull xd_[4][4];
                #pragma unroll
                for (int t = 0; t < 4; t++) {
                    float4 xf4 = *(const float4*)(xrow + t * IU + ih * 4);
                    xd_[t][0] = dup2(xf4.x);
                    xd_[t][1] = dup2(xf4.y);
                    xd_[t][2] = dup2(xf4.z);
                    xd_[t][3] = dup2(xf4.w);
                }
                const ull* wb_ = Wb + (cl * J + jb) * WJS + ih * 32 + sh;
                #pragma unroll
                for (int jj = 0; jj < 5; jj++) {
                    const ull* w = wb_ + jj * WJS;
                    ull w0 = w[0], w1 = w[8], w2 = w[16], w3 = w[24];
                    #pragma unroll
                    for (int t = 0; t < 4; t++) {
                        fma2(acc[jj][t], w0, xd_[t][0]);
                        fma2(acc[jj][t], w1, xd_[t][1]);
                        fma2(acc[jj][t], w2, xd_[t][2]);
                        fma2(acc[jj][t], w3, xd_[t][3]);
                    }
                }
            }
        }
    }
    ull* spb = g_sp2[cg];
    #pragma unroll
    for (int jj = 0; jj < 5; jj++)
        #pragma unroll
        for (int t = 0; t < 4; t++)
            spb[((size_t)(jb + jj) * B + b0 + bt4 * 4 + t) * 8 + sh] = acc[jj][t];
}

// ---------------------------------------------------------------------------
// K_b: partial delta_b[c,j] = sum_{b in tile, s} v * u_hat. Raw W (no cc).
// Direct-u form. PDL: stage static W/x first, wait before reading g_v2
// (written by the preceding k_rs).
// ---------------------------------------------------------------------------
__global__ void __launch_bounds__(NTHR, 1) k_b() {
    extern __shared__ char smraw[];
    SMemB& sm = *(SMemB*)smraw;
    int tid = threadIdx.x;
    int cg = blockIdx.x, bt = blockIdx.y;
    int c0 = cg * CG, b0 = bt * BT;
    int sh  = tid & 7;
    int jb  = ((tid >> 3) & 1) * 5;
    int bt4 = tid >> 4;
    int warp = tid >> 5, lane = tid & 31;

    gdc_launch();
    issue_W(sm.Wp, c0, tid);
    issue_x(sm.xf[0], c0, b0, tid);
    cpcommit();

    gdc_wait();                     // g_v2 written by the preceding k_rs
    ull vv[5][4];
    #pragma unroll
    for (int jj = 0; jj < 5; jj++)
        #pragma unroll
        for (int t = 0; t < 4; t++)
            vv[jj][t] = g_v2[((size_t)(jb + jj) * B + b0 + bt4 * 4 + t) * 8 + sh];

    for (int sc = 0; sc < NSUB; sc++) {
        if (sc > 0) {
            __syncthreads();                 // protects Wp + dsm + x buffer reuse
            issue_W(sm.Wp, c0 + sc * CCB, tid);
            cpcommit();
        }
        if (sc + 1 < NSUB) {
            issue_x(sm.xf[(sc + 1) & 1], c0 + (sc + 1) * CCB, b0, tid);
            cpcommit();
        }
        if (sc + 1 < NSUB) cpwait<1>(); else cpwait<0>();
        __syncthreads();
        const float* xb = sm.xf[sc & 1];

        #pragma unroll 1
        for (int cl = 0; cl < CCB; cl++) {
            ull p2[5] = {0, 0, 0, 0, 0};
            const float* xrow = xb + (cl * BT + bt4 * 4) * IU;
            // load + duplicate all 8 i's for the 4 b's of this thread
            ull xd_[4][8];
            #pragma unroll
            for (int t = 0; t < 4; t++) {
                float4 xa = *(const float4*)(xrow + t * IU);
                float4 xc = *(const float4*)(xrow + t * IU + 4);
                xd_[t][0] = dup2(xa.x); xd_[t][1] = dup2(xa.y);
                xd_[t][2] = dup2(xa.z); xd_[t][3] = dup2(xa.w);
                xd_[t][4] = dup2(xc.x); xd_[t][5] = dup2(xc.y);
                xd_[t][6] = dup2(xc.z); xd_[t][7] = dup2(xc.w);
            }
            const ull* wb_ = sm.Wp + (cl * J + jb) * WJS + sh;
            #pragma unroll
            for (int jj = 0; jj < 5; jj++) {
                const ull* w = wb_ + jj * WJS;
                ull w0 = w[0],  w1 = w[8],  w2 = w[16], w3 = w[24];
                ull w4 = w[32], w5 = w[40], w6 = w[48], w7 = w[56];
                #pragma unroll
                for (int t = 0; t < 4; t++) {
                    ull u;
                    asm("mul.rn.f32x2 %0, %1, %2;" : "=l"(u) : "l"(w0), "l"(xd_[t][0]));
                    fma2(u, w1, xd_[t][1]);
                    fma2(u, w2, xd_[t][2]);
                    fma2(u, w3, xd_[t][3]);
                    fma2(u, w4, xd_[t][4]);
                    fma2(u, w5, xd_[t][5]);
                    fma2(u, w6, xd_[t][6]);
                    fma2(u, w7, xd_[t][7]);
                    fma2(p2[jj], vv[jj][t], u);
                }
            }
            #pragma unroll
            for (int jj = 0; jj < 5; jj++) {
                float p = lo2(p2[jj]) + hi2(p2[jj]);
                p += __shfl_xor_sync(0xffffffffu, p, 1);
                p += __shfl_xor_sync(0xffffffffu, p, 2);
                p += __shfl_xor_sync(0xffffffffu, p, 4);
                p += __shfl_xor_sync(0xffffffffu, p, 16);
                if ((lane & 23) == 0)   // lanes 0 (jg0) and 8 (jg1)
                    sm.dsm[warp * (CCB * J) + cl * J + jb + jj] = p;
            }
        }
        __syncthreads();
        if (tid < CCB * J) {
            float s = 0.f;
            #pragma unroll
            for (int w = 0; w < 16; w++) s += sm.dsm[w * (CCB * J) + tid];
            g_bp[bt][(c0 + sc * CCB + tid / J) * J + tid % J] = s;
        }
    }
}

// ---------------------------------------------------------------------------
// Reduction + squash, 512 threads/block: upper half sums partials 18..35,
// lower half sums 0..17; halves meet through SMEM. PDL: everything depends
// on the preceding k_s -> wait at the top.
// ---------------------------------------------------------------------------
__global__ void __launch_bounds__(512) k_rs(float postscale, float* __restrict__ out) {
    __shared__ ull sh2[256];
    gdc_launch();
    gdc_wait();
    int half = threadIdx.x >> 8;           // 0 or 1
    int t    = threadIdx.x & 255;
    int idx  = blockIdx.x * 256 + t;       // [0, 40960)
    int p0   = half * (NCG / 2);

    ull a0 = g_sp2[p0][idx];
    ull a1 = g_sp2[p0 + 1][idx];
    ull a2 = g_sp2[p0 + 2][idx];
    ull a3 = g_sp2[p0 + 3][idx];
    #pragma unroll
    for (int p = 4; p < NCG / 2 - 2; p += 4) {
        a0 = add2(a0, g_sp2[p0 + p][idx]);
        a1 = add2(a1, g_sp2[p0 + p + 1][idx]);
        a2 = add2(a2, g_sp2[p0 + p + 2][idx]);
        a3 = add2(a3, g_sp2[p0 + p + 3][idx]);
    }
    a0 = add2(a0, g_sp2[p0 + 16][idx]);
    a1 = add2(a1, g_sp2[p0 + 17][idx]);
    ull a = add2(add2(a0, a1), add2(a2, a3));

    if (half) sh2[t] = a;
    __syncthreads();
    if (half) return;
    a = add2(a, sh2[t]);

    float lo = lo2(a) * postscale;
    float hi = hi2(a) * postscale;
    float m = lo * lo + hi * hi;
    m += __shfl_xor_sync(0xffffffffu, m, 1);
    m += __shfl_xor_sync(0xffffffffu, m, 2);
    m += __shfl_xor_sync(0xffffffffu, m, 4);
    float fac = sqrtf(m) / (1.f + m);
    float vlo = lo * fac, vhi = hi * fac;
    g_v2[idx] = pack2(vlo, vhi);
    if (out) {
        int sh = idx & 7;
        int b  = (idx >> 3) & (B - 1);
        int j  = idx >> 12;
        out[(b * J + j) * S + sh]     = vlo;
        out[(b * J + j) * S + sh + 8] = vhi;
    }
}

// ---------------------------------------------------------------------------
// Launch helper: programmatic dependent launch (stream-serialization relaxed;
// the kernel launches when its predecessor triggers, and gdc_wait() inside
// provides the data dependency). Degrades to normal serialization if PDL is
// unsupported.
// ---------------------------------------------------------------------------
template <typename K, typename... Args>
static void launch_pdl(K kernel, dim3 g, dim3 b, size_t smem, Args... args) {
    cudaLaunchConfig_t cfg = {};
    cfg.gridDim = g;
    cfg.blockDim = b;
    cfg.dynamicSmemBytes = smem;
    cfg.stream = 0;
    cudaLaunchAttribute attr[1];
    attr[0].id = cudaLaunchAttributeProgrammaticStreamSerialization;
    attr[0].val.programmaticStreamSerializationAllowed = 1;
    cfg.attrs = attr;
    cfg.numAttrs = 1;
    cudaLaunchKernelEx(&cfg, kernel, args...);
}

// ---------------------------------------------------------------------------
extern "C" void kernel_launch(void* const* d_in, const int* in_sizes, int n_in,
                              void* d_out, int out_size) {
    const float* x = (const float*)d_in[0];   // [512][8][1152]
    const float* W = (const float*)d_in[1];   // [1152][10][16][8]
    float* out = (float*)d_out;               // [512][10][16]

    cudaFuncSetAttribute(k_s<0,0>, cudaFuncAttributeMaxDynamicSharedMemorySize,
                         (int)sizeof(SMemS));
    cudaFuncSetAttribute(k_s<1,0>, cudaFuncAttributeMaxDynamicSharedMemorySize,
                         (int)sizeof(SMemS));
    cudaFuncSetAttribute(k_s<1,1>, cudaFuncAttributeMaxDynamicSharedMemorySize,
                         (int)sizeof(SMemS));
    cudaFuncSetAttribute(k_b, cudaFuncAttributeMaxDynamicSharedMemorySize,
                         (int)sizeof(SMemB));

    k_transpose<<<dim3(C / 32, R / 32), dim3(32, 8)>>>(x);
    k_prepW<<<(C * J * WROW + 255) / 256, 256>>>(W);

    dim3 grid(NCG, NBT);
    dim3 blk(NTHR, 1, 1);
    dim3 rgrid(160, 1, 1);
    dim3 rblk(512, 1, 1);

    // t = 0: uniform cc = 1/J folded as postscale
    launch_pdl(k_s<0,0>, grid, blk, sizeof(SMemS));
    launch_pdl(k_rs, rgrid, rblk, 0, 0.1f, (float*)nullptr);

    // t = 1
    launch_pdl(k_b, grid, blk, sizeof(SMemB));
    launch_pdl(k_s<1,0>, grid, blk, sizeof(SMemS));
    launch_pdl(k_rs, rgrid, rblk, 0, 1.f, (float*)nullptr);

    // t = 2
    launch_pdl(k_b, grid, blk, sizeof(SMemB));
    launch_pdl(k_s<1,1>, grid, blk, sizeof(SMemS));
    launch_pdl(k_rs, rgrid, rblk, 0, 1.f, out);
}